// round 1
// baseline (speedup 1.0000x reference)
#include <cuda_runtime.h>
#include <cuda_bf16.h>

// Skipgram negative-sampling loss.
// Inputs (metadata order): input_idx[N] i32, output_idx[N] i32, neg_idx[N*K] i32,
//                          W_in[100000*128] f32, W_out[100000*128] f32
// Output: scalar f32 loss.

#define NN 65536
#define DD 128
#define KK 10

// Scratch accumulator (allocation-free per harness rules).
__device__ float g_sum;

__device__ __forceinline__ float log_sigmoid(float x) {
    // Stable: log(sigmoid(x)) = min(x,0) - log1p(exp(-|x|)).  |x| <= 128 here.
    return fminf(x, 0.0f) - log1pf(__expf(-fabsf(x)));
}

__global__ void sg_init_kernel() { g_sum = 0.0f; }

__global__ __launch_bounds__(256) void skipgram_kernel(
    const int* __restrict__ input_idx,
    const int* __restrict__ output_idx,
    const int* __restrict__ neg_idx,
    const float4* __restrict__ W_in,    // rows of 32 float4
    const float4* __restrict__ W_out)
{
    const int lane = threadIdx.x & 31;
    const int wid  = threadIdx.x >> 5;
    const int warps_total = (gridDim.x * blockDim.x) >> 5;
    int gwarp = (blockIdx.x * blockDim.x + threadIdx.x) >> 5;

    float local = 0.0f;

    for (int i = gwarp; i < NN; i += warps_total) {
        const int ii = __ldg(&input_idx[i]);
        const int oi = __ldg(&output_idx[i]);

        // Lane 'lane' owns float4 #lane of each 128-float row (32 float4/row).
        const float4 a = __ldg(&W_in[ii * 32 + lane]);

        float dots[KK + 1];
        {
            const float4 b = __ldg(&W_out[oi * 32 + lane]);
            dots[0] = a.x * b.x + a.y * b.y + a.z * b.z + a.w * b.w;
        }
        #pragma unroll
        for (int k = 0; k < KK; k++) {
            const int ni = __ldg(&neg_idx[i * KK + k]);
            const float4 c = __ldg(&W_out[ni * 32 + lane]);
            dots[k + 1] = a.x * c.x + a.y * c.y + a.z * c.z + a.w * c.w;
        }

        // 11 independent butterfly reductions (ILP hides SHFL latency).
        #pragma unroll
        for (int k = 0; k <= KK; k++) {
            float v = dots[k];
            v += __shfl_xor_sync(0xffffffffu, v, 16);
            v += __shfl_xor_sync(0xffffffffu, v, 8);
            v += __shfl_xor_sync(0xffffffffu, v, 4);
            v += __shfl_xor_sync(0xffffffffu, v, 2);
            v += __shfl_xor_sync(0xffffffffu, v, 1);
            dots[k] = v;
        }

        if (lane == 0) {
            float s = log_sigmoid(dots[0]);
            #pragma unroll
            for (int k = 1; k <= KK; k++) s += log_sigmoid(-dots[k]);
            local += s;
        }
    }

    // Block reduction: one value per warp (lane 0), then single atomic per block.
    __shared__ float ssum[8];
    if (lane == 0) ssum[wid] = local;
    __syncthreads();
    if (threadIdx.x == 0) {
        float s = 0.0f;
        #pragma unroll
        for (int w = 0; w < 8; w++) s += ssum[w];
        atomicAdd(&g_sum, s);
    }
}

__global__ void sg_finalize_kernel(float* __restrict__ out) {
    out[0] = g_sum * (1.0f / (float)NN);
}

extern "C" void kernel_launch(void* const* d_in, const int* in_sizes, int n_in,
                              void* d_out, int out_size) {
    const int*    input_idx  = (const int*)d_in[0];
    const int*    output_idx = (const int*)d_in[1];
    const int*    neg_idx    = (const int*)d_in[2];
    const float4* W_in       = (const float4*)d_in[3];
    const float4* W_out      = (const float4*)d_in[4];
    float*        out        = (float*)d_out;

    sg_init_kernel<<<1, 1>>>();
    // 1184 blocks = 8 blocks/SM on 148 SMs, 256 thr each -> 9472 warps grid-striding N.
    skipgram_kernel<<<1184, 256>>>(input_idx, output_idx, neg_idx, W_in, W_out);
    sg_finalize_kernel<<<1, 1>>>(out);
}

// round 2
// speedup vs baseline: 1.8166x; 1.8166x over previous
#include <cuda_runtime.h>
#include <cuda_bf16.h>

// Skipgram negative-sampling loss, single fused kernel.
// Inputs: input_idx[N] i32, output_idx[N] i32, neg_idx[N*K] i32,
//         W_in[100000*128] f32, W_out[100000*128] f32
// Output: scalar f32 loss.

#define NN 65536
#define KK 10
#define GRID 8192           // 8192 blocks * 8 warps = 65536 warps = 1 sample/warp

// Scratch (allocation-free per harness rules). Zero-initialized at module load;
// the last block resets them every launch so graph replays stay correct.
__device__ float    g_sum;
__device__ unsigned g_done;

__device__ __forceinline__ float log_sigmoid(float x) {
    // log(sigmoid(x)) = min(x,0) - log(1 + exp(-|x|)), fast-math flavor.
    // t = exp(-|x|) in (0,1]; __logf(1+t) abs err ~1e-7 -> irrelevant at 1e-3 tol.
    float t = __expf(-fabsf(x));
    return fminf(x, 0.0f) - __logf(1.0f + t);
}

__global__ __launch_bounds__(256, 5) void skipgram_fused_kernel(
    const int* __restrict__ input_idx,
    const int* __restrict__ output_idx,
    const int* __restrict__ neg_idx,
    const float4* __restrict__ W_in,    // rows of 32 float4
    const float4* __restrict__ W_out,
    float* __restrict__ out)
{
    const int lane = threadIdx.x & 31;
    const int wid  = threadIdx.x >> 5;
    const int i    = (blockIdx.x << 3) + wid;   // exactly one sample per warp

    const int ii = __ldg(&input_idx[i]);
    const int oi = __ldg(&output_idx[i]);

    // Lane owns float4 #lane of each 128-float row.
    const float4 a = __ldg(&W_in[ii * 32 + lane]);

    float dots[KK + 1];
    {
        const float4 b = __ldg(&W_out[oi * 32 + lane]);
        dots[0] = fmaf(a.x, b.x, fmaf(a.y, b.y, fmaf(a.z, b.z, a.w * b.w)));
    }
    #pragma unroll
    for (int k = 0; k < KK; k++) {
        const int ni = __ldg(&neg_idx[i * KK + k]);
        const float4 c = __ldg(&W_out[ni * 32 + lane]);
        dots[k + 1] = fmaf(a.x, c.x, fmaf(a.y, c.y, fmaf(a.z, c.z, a.w * c.w)));
    }

    // 11 independent 5-step butterfly reductions; interleaved for ILP.
    #pragma unroll
    for (int s = 16; s > 0; s >>= 1) {
        #pragma unroll
        for (int k = 0; k <= KK; k++)
            dots[k] += __shfl_xor_sync(0xffffffffu, dots[k], s);
    }

    float loss = 0.0f;
    if (lane == 0) {
        loss = log_sigmoid(dots[0]);
        #pragma unroll
        for (int k = 1; k <= KK; k++) loss += log_sigmoid(-dots[k]);
    }

    // Block reduction: 8 warp values -> one atomic per block.
    __shared__ float ssum[8];
    if (lane == 0) ssum[wid] = loss;
    __syncthreads();

    if (threadIdx.x == 0) {
        float s = 0.0f;
        #pragma unroll
        for (int w = 0; w < 8; w++) s += ssum[w];
        atomicAdd(&g_sum, s);
        __threadfence();
        unsigned old = atomicAdd(&g_done, 1u);
        if (old == (unsigned)(GRID - 1)) {
            // Last block: publish result and reset scratch for the next replay.
            float total = atomicAdd(&g_sum, 0.0f);   // atomic read at L2
            out[0] = total * (1.0f / (float)NN);
            g_sum  = 0.0f;
            g_done = 0u;
        }
    }
}

extern "C" void kernel_launch(void* const* d_in, const int* in_sizes, int n_in,
                              void* d_out, int out_size) {
    const int*    input_idx  = (const int*)d_in[0];
    const int*    output_idx = (const int*)d_in[1];
    const int*    neg_idx    = (const int*)d_in[2];
    const float4* W_in       = (const float4*)d_in[3];
    const float4* W_out      = (const float4*)d_in[4];
    float*        out        = (float*)d_out;

    skipgram_fused_kernel<<<GRID, 256>>>(input_idx, output_idx, neg_idx,
                                         W_in, W_out, out);
}

// round 4
// speedup vs baseline: 2.1986x; 1.2102x over previous
#include <cuda_runtime.h>
#include <cuda_bf16.h>

// Skipgram negative-sampling loss, single fused kernel.
// Layout: each 8-lane group of a warp owns one sample (4 samples/warp).
// Lane l of a group owns row float4s {j*8 + l : j=0..3} -> each warp LDG.128
// covers 4 line-aligned 128B segments (one per sample) = full coalescing.

#define NN   65536
#define KK   10
#define GRID 2048            // 2048 blocks * 8 warps * 4 samples = 65536

__device__ float    g_sum;
__device__ unsigned g_done;

__device__ __forceinline__ float log_sigmoid(float x) {
    float t = __expf(-fabsf(x));
    return fminf(x, 0.0f) - __logf(1.0f + t);
}

__device__ __forceinline__ float dot4(float4 a, float4 b) {
    return fmaf(a.x, b.x, fmaf(a.y, b.y, fmaf(a.z, b.z, a.w * b.w)));
}

__global__ __launch_bounds__(256, 4) void skipgram_fused_kernel(
    const int* __restrict__ input_idx,
    const int* __restrict__ output_idx,
    const int* __restrict__ neg_idx,
    const float4* __restrict__ W_in,    // rows of 32 float4
    const float4* __restrict__ W_out,
    float* __restrict__ out)
{
    const int lane = threadIdx.x & 31;
    const int wid  = threadIdx.x >> 5;
    const int g    = lane >> 3;         // group 0..3 within warp
    const int l    = lane & 7;          // lane 0..7 within group
    const int i    = ((((blockIdx.x << 3) | wid) << 2) | g);  // sample id

    const int ii = __ldg(&input_idx[i]);
    const int oi = __ldg(&output_idx[i]);

    // a-row: 4 float4 per lane, addresses base + j*8 + l (contiguous per group, per j)
    const float4* arow = W_in + ii * 32 + l;
    const float4 a0 = __ldg(arow +  0);
    const float4 a1 = __ldg(arow +  8);
    const float4 a2 = __ldg(arow + 16);
    const float4 a3 = __ldg(arow + 24);

    float dots[KK + 1];
    {
        const float4* brow = W_out + oi * 32 + l;
        dots[0] = dot4(a0, __ldg(brow +  0)) + dot4(a1, __ldg(brow +  8))
                + dot4(a2, __ldg(brow + 16)) + dot4(a3, __ldg(brow + 24));
    }
    #pragma unroll
    for (int k = 0; k < KK; k++) {
        const int ni = __ldg(&neg_idx[i * KK + k]);   // uniform within group
        const float4* crow = W_out + ni * 32 + l;
        dots[k + 1] = dot4(a0, __ldg(crow +  0)) + dot4(a1, __ldg(crow +  8))
                    + dot4(a2, __ldg(crow + 16)) + dot4(a3, __ldg(crow + 24));
    }

    // Reduce within 8-lane groups: 3 butterfly steps, 11 dots, all 4 samples at once.
    #pragma unroll
    for (int s = 4; s > 0; s >>= 1) {
        #pragma unroll
        for (int k = 0; k <= KK; k++)
            dots[k] += __shfl_xor_sync(0xffffffffu, dots[k], s);
    }

    float loss = 0.0f;
    if (l == 0) {   // 4 group leaders per warp
        loss = log_sigmoid(dots[0]);
        #pragma unroll
        for (int k = 1; k <= KK; k++) loss += log_sigmoid(-dots[k]);
    }

    // Block reduction: 32 leader values (8 warps * 4 groups) -> one atomic.
    __shared__ float ssum[32];
    if (l == 0) ssum[(wid << 2) | g] = loss;
    __syncthreads();

    if (threadIdx.x == 0) {
        float s = 0.0f;
        #pragma unroll
        for (int w = 0; w < 32; w++) s += ssum[w];
        atomicAdd(&g_sum, s);
        __threadfence();
        unsigned old = atomicAdd(&g_done, 1u);
        if (old == (unsigned)(GRID - 1)) {
            float total = atomicAdd(&g_sum, 0.0f);
            out[0] = total * (1.0f / (float)NN);
            g_sum  = 0.0f;
            g_done = 0u;
        }
    }
}

extern "C" void kernel_launch(void* const* d_in, const int* in_sizes, int n_in,
                              void* d_out, int out_size) {
    const int*    input_idx  = (const int*)d_in[0];
    const int*    output_idx = (const int*)d_in[1];
    const int*    neg_idx    = (const int*)d_in[2];
    const float4* W_in       = (const float4*)d_in[3];
    const float4* W_out      = (const float4*)d_in[4];
    float*        out        = (float*)d_out;

    skipgram_fused_kernel<<<GRID, 256>>>(input_idx, output_idx, neg_idx,
                                         W_in, W_out, out);
}